// round 14
// baseline (speedup 1.0000x reference)
#include <cuda_runtime.h>

#define S_   512
#define H_   16
#define D_   24
#define DS_  384
#define CZ_  128
#define EPS_ 1e-5f
#define SCALE_ 0.20412414523193152f   // 24^-0.5

typedef unsigned long long ull;

// packed fp32x2 FMA (bit-exact pairwise fp32; sm_100+ PTX)
#define FMA2(acc, a, b) \
    asm("fma.rn.f32x2 %0, %1, %2, %0;" : "+l"(acc) : "l"(a), "l"(b))
#define PACKDUP(d, a) \
    asm("mov.b64 %0, {%1, %1};" : "=l"(d) : "r"(__float_as_uint(a)))
#define LO_(v) __uint_as_float((unsigned)(v))
#define HI_(v) __uint_as_float((unsigned)((v) >> 32))

// -------- scratch (no allocations allowed) --------
__device__ float g_qt[H_*S_*D_];      // [H][S][D], q pre-scaled by D^-0.5
__device__ float g_kt[H_*S_*D_];
__device__ float g_vt[H_*S_*D_];
__device__ float g_g[S_*DS_];
__device__ float g_o[S_*DS_];
__device__ float g_bias[H_*S_*S_];    // includes seq_mask

// ============================================================
// bias = LN(z) @ z_w^T + mask -> g_bias[H][S][S]
// Step C now FFMA2: 16 FFMA2 + 6 LDS.128 per c4 (64 FMA).
// ============================================================
#define LDX_ 132

extern __shared__ float smx[];
__global__ __launch_bounds__(256) void bias_kernel(
    const float* __restrict__ z, const float* __restrict__ mask,
    const float* __restrict__ lnw, const float* __restrict__ lnb,
    const float* __restrict__ zw)
{
    float* Y  = smx;                  // 128*132
    float* ZW = smx + 128*LDX_;       // 16*128
    float* MS = ZW + 16*CZ_;          // 128
    const int tid = threadIdx.x;
    const int r0  = blockIdx.x * 128;
    const int i_  = r0 >> 9;
    const int j0  = r0 & 511;

    // ---- A: stage ----
    #pragma unroll
    for (int it = 0; it < 16; it++) {
        const int l = tid + it*256;
        const int row = l >> 5, c4 = l & 31;
        *(float4*)&Y[row*LDX_ + c4*4] =
            *(const float4*)&z[(size_t)(r0 + row)*CZ_ + c4*4];
    }
    #pragma unroll
    for (int it = 0; it < 2; it++)
        ((float4*)ZW)[tid + it*256] = ((const float4*)zw)[tid + it*256];
    if (tid < 32) ((float4*)MS)[tid] = ((const float4*)(mask + j0))[tid];
    __syncthreads();

    // ---- B: layernorm in place (2 threads per row) ----
    {
        const int row  = tid >> 1;
        const int base = (tid & 1) * 64;
        float* xr = &Y[row*LDX_ + base];
        float sum = 0.f, ssq = 0.f;
        #pragma unroll
        for (int c = 0; c < 16; c++) {
            const float4 v = *(const float4*)&xr[c*4];
            sum += v.x + v.y + v.z + v.w;
            ssq += v.x*v.x + v.y*v.y + v.z*v.z + v.w*v.w;
        }
        sum += __shfl_xor_sync(0xffffffffu, sum, 1);
        ssq += __shfl_xor_sync(0xffffffffu, ssq, 1);
        const float mu   = sum * (1.f/CZ_);
        const float var_ = ssq * (1.f/CZ_) - mu*mu;
        const float rinv = rsqrtf(var_ + EPS_);
        #pragma unroll
        for (int c = 0; c < 16; c++) {
            const float4 v  = *(const float4*)&xr[c*4];
            const float4 w4 = *(const float4*)&lnw[base + c*4];
            const float4 b4 = *(const float4*)&lnb[base + c*4];
            float4 y;
            y.x = (v.x - mu)*rinv*w4.x + b4.x;
            y.y = (v.y - mu)*rinv*w4.y + b4.y;
            y.z = (v.z - mu)*rinv*w4.z + b4.z;
            y.w = (v.w - mu)*rinv*w4.w + b4.w;
            *(float4*)&xr[c*4] = y;
        }
    }
    __syncthreads();

    // ---- C: C[128,16] = Y @ zw^T  (FFMA2; thread: rows r,r+64 x 4 heads) ----
    {
        const int r  = tid & 63;
        const int hb = (tid >> 6) * 4;      // warp-uniform head quad
        const ulonglong2* y0p = (const ulonglong2*)&Y[r*LDX_];
        const ulonglong2* y1p = (const ulonglong2*)&Y[(r + 64)*LDX_];
        const ulonglong2* wp0 = (const ulonglong2*)&ZW[(hb+0)*CZ_];
        const ulonglong2* wp1 = (const ulonglong2*)&ZW[(hb+1)*CZ_];
        const ulonglong2* wp2 = (const ulonglong2*)&ZW[(hb+2)*CZ_];
        const ulonglong2* wp3 = (const ulonglong2*)&ZW[(hb+3)*CZ_];
        ull acc2[2][4] = {};
        #pragma unroll 4
        for (int c4 = 0; c4 < 32; c4++) {
            const ulonglong2 y0 = y0p[c4];
            const ulonglong2 y1 = y1p[c4];
            const ulonglong2 w0 = wp0[c4], w1 = wp1[c4], w2 = wp2[c4], w3 = wp3[c4];
            FMA2(acc2[0][0], y0.x, w0.x); FMA2(acc2[0][0], y0.y, w0.y);
            FMA2(acc2[0][1], y0.x, w1.x); FMA2(acc2[0][1], y0.y, w1.y);
            FMA2(acc2[0][2], y0.x, w2.x); FMA2(acc2[0][2], y0.y, w2.y);
            FMA2(acc2[0][3], y0.x, w3.x); FMA2(acc2[0][3], y0.y, w3.y);
            FMA2(acc2[1][0], y1.x, w0.x); FMA2(acc2[1][0], y1.y, w0.y);
            FMA2(acc2[1][1], y1.x, w1.x); FMA2(acc2[1][1], y1.y, w1.y);
            FMA2(acc2[1][2], y1.x, w2.x); FMA2(acc2[1][2], y1.y, w2.y);
            FMA2(acc2[1][3], y1.x, w3.x); FMA2(acc2[1][3], y1.y, w3.y);
        }
        const float mk0 = MS[r], mk1 = MS[r + 64];
        #pragma unroll
        for (int h = 0; h < 4; h++) {
            g_bias[((hb + h)*S_ + i_)*S_ + j0 + r] =
                LO_(acc2[0][h]) + HI_(acc2[0][h]) + mk0;
            g_bias[((hb + h)*S_ + i_)*S_ + j0 + r + 64] =
                LO_(acc2[1][h]) + HI_(acc2[1][h]) + mk1;
        }
    }
}

// ============================================================
// QKVG GEMMs: 32x64 tiles, FFMA2 microtile (2m x 2 f32x2-n),
// double-buffered global prefetch. 384 blocks.
// ============================================================
__global__ __launch_bounds__(256) void gemm_qkvg_kernel(
    const float* __restrict__ s,
    const float* __restrict__ qw, const float* __restrict__ qb,
    const float* __restrict__ kw, const float* __restrict__ vw,
    const float* __restrict__ gw)
{
    __shared__ float As[32][34];
    __shared__ float Bs[32][68];
    const int var = blockIdx.z;
    const int m0  = blockIdx.y * 32;
    const int n0  = blockIdx.x * 64;
    const float* W = (var==0)?qw:(var==1)?kw:(var==2)?vw:gw;
    const int tid = threadIdx.x;
    const int tx = tid & 15, ty = tid >> 4;
    const int lk = tid & 31, lm = tid >> 5;
    ull acc2[2][2] = {};
    float pa[4], pb[8];

    #pragma unroll
    for (int i = 0; i < 4; i++) pa[i] = s[(m0 + lm + 8*i)*DS_ + lk];
    #pragma unroll
    for (int i = 0; i < 8; i++) pb[i] = W[(n0 + lm + 8*i)*DS_ + lk];

    for (int k0 = 0; k0 < DS_; k0 += 32) {
        #pragma unroll
        for (int i = 0; i < 4; i++) As[lk][lm + 8*i] = pa[i];
        #pragma unroll
        for (int i = 0; i < 8; i++) Bs[lk][lm + 8*i] = pb[i];
        __syncthreads();
        if (k0 + 32 < DS_) {
            #pragma unroll
            for (int i = 0; i < 4; i++) pa[i] = s[(m0 + lm + 8*i)*DS_ + k0 + 32 + lk];
            #pragma unroll
            for (int i = 0; i < 8; i++) pb[i] = W[(n0 + lm + 8*i)*DS_ + k0 + 32 + lk];
        }
        #pragma unroll
        for (int kk = 0; kk < 32; kk++) {
            const float2 a = *(const float2*)&As[kk][ty*2];
            const ulonglong2 b2 = *(const ulonglong2*)&Bs[kk][tx*4];
            ull aa0, aa1;
            PACKDUP(aa0, a.x);
            PACKDUP(aa1, a.y);
            FMA2(acc2[0][0], aa0, b2.x); FMA2(acc2[0][1], aa0, b2.y);
            FMA2(acc2[1][0], aa1, b2.x); FMA2(acc2[1][1], aa1, b2.y);
        }
        __syncthreads();
    }

    const int col = n0 + tx*4;
    #pragma unroll
    for (int i = 0; i < 2; i++) {
        const int row = m0 + ty*2 + i;
        float4 rv = make_float4(LO_(acc2[i][0]), HI_(acc2[i][0]),
                                LO_(acc2[i][1]), HI_(acc2[i][1]));
        if (var == 0) {
            rv.x += qb[col]; rv.y += qb[col+1]; rv.z += qb[col+2]; rv.w += qb[col+3];
            rv.x *= SCALE_; rv.y *= SCALE_; rv.z *= SCALE_; rv.w *= SCALE_;
        }
        if (var == 3) {
            rv.x = 1.f/(1.f+__expf(-rv.x));
            rv.y = 1.f/(1.f+__expf(-rv.y));
            rv.z = 1.f/(1.f+__expf(-rv.z));
            rv.w = 1.f/(1.f+__expf(-rv.w));
            *(float4*)&g_g[row*DS_ + col] = rv;
        } else {
            const int hh = col / D_;
            const int dd = col - hh*D_;
            float* dst = (var==0) ? g_qt : (var==1) ? g_kt : g_vt;
            *(float4*)&dst[(hh*S_ + row)*D_ + dd] = rv;
        }
    }
}

// ============================================================
// attention: FFMA2 in scores + PV. Same layout/sync as before.
// ============================================================
extern __shared__ float sma[];
__global__ __launch_bounds__(256) void attn_kernel()
{
    float* sc   = sma;                       // [32][513]
    float* kv   = sma + 32*513;              // [128][28]
    float* part = sma + 32*513 + 128*28;     // [8][32][25]
    const int h    = blockIdx.y;
    const int qi0  = blockIdx.x * 32;
    const int tid  = threadIdx.x;
    const int lane = tid & 31;
    const int w    = tid >> 5;
    const int qib  = w * 4;

    // q rows in registers as f32x2 pairs
    ull qr2[4][12];
    #pragma unroll
    for (int i = 0; i < 4; i++) {
        const ulonglong2* qp = (const ulonglong2*)&g_qt[(h*S_ + qi0 + qib + i)*D_];
        #pragma unroll
        for (int c = 0; c < 6; c++) {
            const ulonglong2 v = qp[c];
            qr2[i][2*c] = v.x; qr2[i][2*c+1] = v.y;
        }
    }

    const float* bias_row = &g_bias[(h*S_ + qi0 + qib)*S_];

    // ---- scores over 4 kj-tiles of 128 ----
    #pragma unroll 1
    for (int tt = 0; tt < 4; tt++) {
        const float4* src = (const float4*)&g_kt[(h*S_ + tt*128)*D_];
        #pragma unroll
        for (int it = 0; it < 3; it++) {
            const int f = tid + it*256;
            const float4 v = src[f];
            const int e0 = f*4;
            const int kjl = e0 / 24, d0 = e0 - kjl*24;
            *(float4*)&kv[kjl*28 + d0] = v;
        }
        __syncthreads();

        #pragma unroll
        for (int ul = 0; ul < 4; ul++) {
            const int kjl = lane + 32*ul;
            const int kj  = tt*128 + kjl;
            const ulonglong2* kp = (const ulonglong2*)&kv[kjl*28];
            ull acc2[4] = {};
            #pragma unroll
            for (int c = 0; c < 6; c++) {
                const ulonglong2 k2 = kp[c];
                FMA2(acc2[0], qr2[0][2*c], k2.x); FMA2(acc2[0], qr2[0][2*c+1], k2.y);
                FMA2(acc2[1], qr2[1][2*c], k2.x); FMA2(acc2[1], qr2[1][2*c+1], k2.y);
                FMA2(acc2[2], qr2[2][2*c], k2.x); FMA2(acc2[2], qr2[2][2*c+1], k2.y);
                FMA2(acc2[3], qr2[3][2*c], k2.x); FMA2(acc2[3], qr2[3][2*c+1], k2.y);
            }
            sc[(qib+0)*513 + kj] = LO_(acc2[0]) + HI_(acc2[0]) + bias_row[0*S_ + kj];
            sc[(qib+1)*513 + kj] = LO_(acc2[1]) + HI_(acc2[1]) + bias_row[1*S_ + kj];
            sc[(qib+2)*513 + kj] = LO_(acc2[2]) + HI_(acc2[2]) + bias_row[2*S_ + kj];
            sc[(qib+3)*513 + kj] = LO_(acc2[3]) + HI_(acc2[3]) + bias_row[3*S_ + kj];
        }
        __syncthreads();
    }

    // ---- softmax: warp owns its 4 rows ----
    #pragma unroll 1
    for (int rr = 0; rr < 4; rr++) {
        float* p = &sc[(qib + rr)*513];
        float mx = -1e30f;
        #pragma unroll
        for (int t = 0; t < 16; t++) mx = fmaxf(mx, p[lane + 32*t]);
        #pragma unroll
        for (int m = 16; m >= 1; m >>= 1) mx = fmaxf(mx, __shfl_xor_sync(0xffffffffu, mx, m));
        float e[16];
        float sum = 0.f;
        #pragma unroll
        for (int t = 0; t < 16; t++) { e[t] = __expf(p[lane + 32*t] - mx); sum += e[t]; }
        #pragma unroll
        for (int m = 16; m >= 1; m >>= 1) sum += __shfl_xor_sync(0xffffffffu, sum, m);
        const float rinv = 1.f / sum;
        #pragma unroll
        for (int t = 0; t < 16; t++) p[lane + 32*t] = e[t]*rinv;
    }
    __syncthreads();

    // ---- PV: FFMA2; thread = (qi=lane, 24 d as 12 f32x2) ----
    {
        const int qi = lane;
        ull acc2[12] = {};

        #pragma unroll 1
        for (int tt = 0; tt < 4; tt++) {
            const float4* src = (const float4*)&g_vt[(h*S_ + tt*128)*D_];
            #pragma unroll
            for (int it = 0; it < 3; it++) {
                const int f = tid + it*256;
                const float4 v = src[f];
                const int e0 = f*4;
                const int kjl = e0 / 24, d0 = e0 - kjl*24;
                *(float4*)&kv[kjl*28 + d0] = v;
            }
            __syncthreads();

            const float* prow = &sc[qi*513 + tt*128];
            #pragma unroll 2
            for (int kk = 0; kk < 16; kk++) {
                const int kjl = w*16 + kk;
                const float pv = prow[kjl];
                ull pvp; PACKDUP(pvp, pv);
                const ulonglong2* vp = (const ulonglong2*)&kv[kjl*28];
                #pragma unroll
                for (int c = 0; c < 6; c++) {
                    const ulonglong2 v2 = vp[c];
                    FMA2(acc2[2*c],   pvp, v2.x);
                    FMA2(acc2[2*c+1], pvp, v2.y);
                }
            }
            __syncthreads();
        }

        float* pp = &part[(w*32 + qi)*25];
        #pragma unroll
        for (int c = 0; c < 12; c++) {
            pp[2*c]   = LO_(acc2[c]);
            pp[2*c+1] = HI_(acc2[c]);
        }
    }
    __syncthreads();

    // reduce 8 warps and store
    for (int e = tid; e < 32*24; e += 256) {
        const int qi = e / 24, d = e - qi*24;
        float sum = 0.f;
        #pragma unroll
        for (int ww = 0; ww < 8; ww++) sum += part[(ww*32 + qi)*25 + d];
        g_o[(qi0 + qi)*DS_ + h*D_ + d] = sum;
    }
}

// ============================================================
// out = (o * g) @ o_w^T : 16x64 tiles (192 blocks), FFMA2.
// ============================================================
__global__ __launch_bounds__(256) void gemm_out_kernel(
    const float* __restrict__ W, float* __restrict__ C)
{
    __shared__ float As[32][17];
    __shared__ float Bs[32][68];
    const int n0 = blockIdx.x*64, m0 = blockIdx.y*16;
    const int tid = threadIdx.x;
    const int tx = tid & 15, ty = tid >> 4;
    const int lk = tid & 31, lm = tid >> 5;
    ull acc2[2] = {};
    float pa[2], pb[8];

    #pragma unroll
    for (int i = 0; i < 2; i++) {
        const int ai = (m0 + lm + 8*i)*DS_ + lk;
        pa[i] = g_o[ai] * g_g[ai];
    }
    #pragma unroll
    for (int i = 0; i < 8; i++) pb[i] = W[(n0 + lm + 8*i)*DS_ + lk];

    for (int k0 = 0; k0 < DS_; k0 += 32) {
        #pragma unroll
        for (int i = 0; i < 2; i++) As[lk][lm + 8*i] = pa[i];
        #pragma unroll
        for (int i = 0; i < 8; i++) Bs[lk][lm + 8*i] = pb[i];
        __syncthreads();
        if (k0 + 32 < DS_) {
            #pragma unroll
            for (int i = 0; i < 2; i++) {
                const int ai = (m0 + lm + 8*i)*DS_ + k0 + 32 + lk;
                pa[i] = g_o[ai] * g_g[ai];
            }
            #pragma unroll
            for (int i = 0; i < 8; i++) pb[i] = W[(n0 + lm + 8*i)*DS_ + k0 + 32 + lk];
        }
        #pragma unroll
        for (int kk = 0; kk < 32; kk++) {
            const float a = As[kk][ty];
            const ulonglong2 b2 = *(const ulonglong2*)&Bs[kk][tx*4];
            ull aa; PACKDUP(aa, a);
            FMA2(acc2[0], aa, b2.x);
            FMA2(acc2[1], aa, b2.y);
        }
        __syncthreads();
    }
    *(float4*)&C[(m0 + ty)*DS_ + n0 + tx*4] =
        make_float4(LO_(acc2[0]), HI_(acc2[0]), LO_(acc2[1]), HI_(acc2[1]));
}

// ============================================================
extern "C" void kernel_launch(void* const* d_in, const int* in_sizes, int n_in,
                              void* d_out, int out_size)
{
    const float* s   = (const float*)d_in[0];
    const float* z   = (const float*)d_in[1];
    const float* msk = (const float*)d_in[2];
    const float* qw  = (const float*)d_in[3];
    const float* qb  = (const float*)d_in[4];
    const float* kw  = (const float*)d_in[5];
    const float* vw  = (const float*)d_in[6];
    const float* gw  = (const float*)d_in[7];
    const float* ow  = (const float*)d_in[8];
    const float* lnw = (const float*)d_in[9];
    const float* lnb = (const float*)d_in[10];
    const float* zw  = (const float*)d_in[11];
    float* out = (float*)d_out;

    const int smem_bias = (128*LDX_ + 16*CZ_ + 128) * 4;        // 76352 B
    const int smem_attn = (32*513 + 128*28 + 8*32*25) * 4;      // 105600 B
    cudaFuncSetAttribute(bias_kernel, cudaFuncAttributeMaxDynamicSharedMemorySize, smem_bias);
    cudaFuncSetAttribute(attn_kernel, cudaFuncAttributeMaxDynamicSharedMemorySize, smem_attn);

    gemm_qkvg_kernel<<<dim3(6, 16, 4), 256>>>(s, qw, qb, kw, vw, gw);
    bias_kernel<<<2048, 256, smem_bias>>>(z, msk, lnw, lnb, zw);
    attn_kernel<<<dim3(16, 16), 256, smem_attn>>>();
    gemm_out_kernel<<<dim3(6, 32), 256>>>(ow, out);
}

// round 15
// speedup vs baseline: 1.1070x; 1.1070x over previous
#include <cuda_runtime.h>

#define S_   512
#define H_   16
#define D_   24
#define DS_  384
#define CZ_  128
#define EPS_ 1e-5f
#define SCALE_ 0.20412414523193152f   // 24^-0.5

typedef unsigned long long ull;

// packed fp32x2 FMA (bit-exact pairwise fp32; sm_100+ PTX)
#define FMA2(acc, a, b) \
    asm("fma.rn.f32x2 %0, %1, %2, %0;" : "+l"(acc) : "l"(a), "l"(b))
#define PACKDUP(d, a) \
    asm("mov.b64 %0, {%1, %1};" : "=l"(d) : "r"(__float_as_uint(a)))
#define LO_(v) __uint_as_float((unsigned)(v))
#define HI_(v) __uint_as_float((unsigned)((v) >> 32))

// -------- scratch (no allocations allowed) --------
__device__ float g_qt[H_*S_*D_];      // [H][S][D], q pre-scaled by D^-0.5
__device__ float g_kt[H_*S_*D_];
__device__ float g_vt[H_*S_*D_];
__device__ float g_g[S_*DS_];
__device__ float g_o[S_*DS_];
__device__ float g_bias[H_*S_*S_];    // includes seq_mask

#define LDX_ 132
#define NG_  384     // gemm blocks in fused kernel

// ============================================================
// FUSED: blocks [0,NG_) = QKVG GEMMs (alias dynamic smem),
//        blocks [NG_,NG_+2048) = bias tiles.
// Same 256-thr shape + same 76KB footprint -> 3 blocks/SM both
// paths; memory-bound bias overlaps compute-bound GEMM.
// ============================================================
extern __shared__ float smx[];
__global__ __launch_bounds__(256) void fused_qkvg_bias_kernel(
    const float* __restrict__ s,
    const float* __restrict__ qw, const float* __restrict__ qb,
    const float* __restrict__ kw, const float* __restrict__ vw,
    const float* __restrict__ gw,
    const float* __restrict__ z, const float* __restrict__ mask,
    const float* __restrict__ lnw, const float* __restrict__ lnb,
    const float* __restrict__ zw)
{
    const int tid = threadIdx.x;

    if (blockIdx.x < NG_) {
        // ---------------- QKVG GEMM path (round-12 verified core) ----------------
        float* As = smx;             // [32][34]  idx kk*34+m
        float* Bs = smx + 32*34;     // [32][68]  idx kk*68+n
        const int b   = blockIdx.x;
        const int var = b / 96;
        const int r   = b % 96;
        const int n0  = (r % 6) * 64;
        const int m0  = (r / 6) * 32;
        const float* W = (var==0)?qw:(var==1)?kw:(var==2)?vw:gw;
        const int tx = tid & 15, ty = tid >> 4;
        const int lk = tid & 31, lm = tid >> 5;
        ull acc2[2][2] = {};
        float pa[4], pb[8];

        #pragma unroll
        for (int i = 0; i < 4; i++) pa[i] = s[(m0 + lm + 8*i)*DS_ + lk];
        #pragma unroll
        for (int i = 0; i < 8; i++) pb[i] = W[(n0 + lm + 8*i)*DS_ + lk];

        for (int k0 = 0; k0 < DS_; k0 += 32) {
            #pragma unroll
            for (int i = 0; i < 4; i++) As[lk*34 + lm + 8*i] = pa[i];
            #pragma unroll
            for (int i = 0; i < 8; i++) Bs[lk*68 + lm + 8*i] = pb[i];
            __syncthreads();
            if (k0 + 32 < DS_) {
                #pragma unroll
                for (int i = 0; i < 4; i++) pa[i] = s[(m0 + lm + 8*i)*DS_ + k0 + 32 + lk];
                #pragma unroll
                for (int i = 0; i < 8; i++) pb[i] = W[(n0 + lm + 8*i)*DS_ + k0 + 32 + lk];
            }
            #pragma unroll
            for (int kk = 0; kk < 32; kk++) {
                const float2 a = *(const float2*)&As[kk*34 + ty*2];
                const ulonglong2 b2 = *(const ulonglong2*)&Bs[kk*68 + tx*4];
                ull aa0, aa1;
                PACKDUP(aa0, a.x);
                PACKDUP(aa1, a.y);
                FMA2(acc2[0][0], aa0, b2.x); FMA2(acc2[0][1], aa0, b2.y);
                FMA2(acc2[1][0], aa1, b2.x); FMA2(acc2[1][1], aa1, b2.y);
            }
            __syncthreads();
        }

        const int col = n0 + tx*4;
        #pragma unroll
        for (int i = 0; i < 2; i++) {
            const int row = m0 + ty*2 + i;
            float4 rv = make_float4(LO_(acc2[i][0]), HI_(acc2[i][0]),
                                    LO_(acc2[i][1]), HI_(acc2[i][1]));
            if (var == 0) {
                rv.x += qb[col]; rv.y += qb[col+1]; rv.z += qb[col+2]; rv.w += qb[col+3];
                rv.x *= SCALE_; rv.y *= SCALE_; rv.z *= SCALE_; rv.w *= SCALE_;
            }
            if (var == 3) {
                rv.x = 1.f/(1.f+__expf(-rv.x));
                rv.y = 1.f/(1.f+__expf(-rv.y));
                rv.z = 1.f/(1.f+__expf(-rv.z));
                rv.w = 1.f/(1.f+__expf(-rv.w));
                *(float4*)&g_g[row*DS_ + col] = rv;
            } else {
                const int hh = col / D_;
                const int dd = col - hh*D_;
                float* dst = (var==0) ? g_qt : (var==1) ? g_kt : g_vt;
                *(float4*)&dst[(hh*S_ + row)*D_ + dd] = rv;
            }
        }
    } else {
        // ---------------- bias path (round-12 verified core) ----------------
        float* Y  = smx;                  // 128*132
        float* ZW = smx + 128*LDX_;       // 16*128
        float* MS = ZW + 16*CZ_;          // 128
        const int r0  = (blockIdx.x - NG_) * 128;
        const int i_  = r0 >> 9;
        const int j0  = r0 & 511;

        // A: stage
        #pragma unroll
        for (int it = 0; it < 16; it++) {
            const int l = tid + it*256;
            const int row = l >> 5, c4 = l & 31;
            *(float4*)&Y[row*LDX_ + c4*4] =
                *(const float4*)&z[(size_t)(r0 + row)*CZ_ + c4*4];
        }
        #pragma unroll
        for (int it = 0; it < 2; it++)
            ((float4*)ZW)[tid + it*256] = ((const float4*)zw)[tid + it*256];
        if (tid < 32) ((float4*)MS)[tid] = ((const float4*)(mask + j0))[tid];
        __syncthreads();

        // B: layernorm in place (2 threads per row)
        {
            const int row  = tid >> 1;
            const int base = (tid & 1) * 64;
            float* xr = &Y[row*LDX_ + base];
            float sum = 0.f, ssq = 0.f;
            #pragma unroll
            for (int c = 0; c < 16; c++) {
                const float4 v = *(const float4*)&xr[c*4];
                sum += v.x + v.y + v.z + v.w;
                ssq += v.x*v.x + v.y*v.y + v.z*v.z + v.w*v.w;
            }
            sum += __shfl_xor_sync(0xffffffffu, sum, 1);
            ssq += __shfl_xor_sync(0xffffffffu, ssq, 1);
            const float mu   = sum * (1.f/CZ_);
            const float var_ = ssq * (1.f/CZ_) - mu*mu;
            const float rinv = rsqrtf(var_ + EPS_);
            #pragma unroll
            for (int c = 0; c < 16; c++) {
                const float4 v  = *(const float4*)&xr[c*4];
                const float4 w4 = *(const float4*)&lnw[base + c*4];
                const float4 b4 = *(const float4*)&lnb[base + c*4];
                float4 y;
                y.x = (v.x - mu)*rinv*w4.x + b4.x;
                y.y = (v.y - mu)*rinv*w4.y + b4.y;
                y.z = (v.z - mu)*rinv*w4.z + b4.z;
                y.w = (v.w - mu)*rinv*w4.w + b4.w;
                *(float4*)&xr[c*4] = y;
            }
        }
        __syncthreads();

        // C: C[128,16] = Y @ zw^T (FFMA2)
        {
            const int r  = tid & 63;
            const int hb = (tid >> 6) * 4;
            const ulonglong2* y0p = (const ulonglong2*)&Y[r*LDX_];
            const ulonglong2* y1p = (const ulonglong2*)&Y[(r + 64)*LDX_];
            const ulonglong2* wp0 = (const ulonglong2*)&ZW[(hb+0)*CZ_];
            const ulonglong2* wp1 = (const ulonglong2*)&ZW[(hb+1)*CZ_];
            const ulonglong2* wp2 = (const ulonglong2*)&ZW[(hb+2)*CZ_];
            const ulonglong2* wp3 = (const ulonglong2*)&ZW[(hb+3)*CZ_];
            ull acc2[2][4] = {};
            #pragma unroll 4
            for (int c4 = 0; c4 < 32; c4++) {
                const ulonglong2 y0 = y0p[c4];
                const ulonglong2 y1 = y1p[c4];
                const ulonglong2 w0 = wp0[c4], w1 = wp1[c4], w2 = wp2[c4], w3 = wp3[c4];
                FMA2(acc2[0][0], y0.x, w0.x); FMA2(acc2[0][0], y0.y, w0.y);
                FMA2(acc2[0][1], y0.x, w1.x); FMA2(acc2[0][1], y0.y, w1.y);
                FMA2(acc2[0][2], y0.x, w2.x); FMA2(acc2[0][2], y0.y, w2.y);
                FMA2(acc2[0][3], y0.x, w3.x); FMA2(acc2[0][3], y0.y, w3.y);
                FMA2(acc2[1][0], y1.x, w0.x); FMA2(acc2[1][0], y1.y, w0.y);
                FMA2(acc2[1][1], y1.x, w1.x); FMA2(acc2[1][1], y1.y, w1.y);
                FMA2(acc2[1][2], y1.x, w2.x); FMA2(acc2[1][2], y1.y, w2.y);
                FMA2(acc2[1][3], y1.x, w3.x); FMA2(acc2[1][3], y1.y, w3.y);
            }
            const float mk0 = MS[r], mk1 = MS[r + 64];
            #pragma unroll
            for (int h = 0; h < 4; h++) {
                g_bias[((hb + h)*S_ + i_)*S_ + j0 + r] =
                    LO_(acc2[0][h]) + HI_(acc2[0][h]) + mk0;
                g_bias[((hb + h)*S_ + i_)*S_ + j0 + r + 64] =
                    LO_(acc2[1][h]) + HI_(acc2[1][h]) + mk1;
            }
        }
    }
}

// ============================================================
// attention: unchanged round-12 FFMA2 version.
// ============================================================
extern __shared__ float sma[];
__global__ __launch_bounds__(256) void attn_kernel()
{
    float* sc   = sma;                       // [32][513]
    float* kv   = sma + 32*513;              // [128][28]
    float* part = sma + 32*513 + 128*28;     // [8][32][25]
    const int h    = blockIdx.y;
    const int qi0  = blockIdx.x * 32;
    const int tid  = threadIdx.x;
    const int lane = tid & 31;
    const int w    = tid >> 5;
    const int qib  = w * 4;

    ull qr2[4][12];
    #pragma unroll
    for (int i = 0; i < 4; i++) {
        const ulonglong2* qp = (const ulonglong2*)&g_qt[(h*S_ + qi0 + qib + i)*D_];
        #pragma unroll
        for (int c = 0; c < 6; c++) {
            const ulonglong2 v = qp[c];
            qr2[i][2*c] = v.x; qr2[i][2*c+1] = v.y;
        }
    }

    const float* bias_row = &g_bias[(h*S_ + qi0 + qib)*S_];

    #pragma unroll 1
    for (int tt = 0; tt < 4; tt++) {
        const float4* src = (const float4*)&g_kt[(h*S_ + tt*128)*D_];
        #pragma unroll
        for (int it = 0; it < 3; it++) {
            const int f = tid + it*256;
            const float4 v = src[f];
            const int e0 = f*4;
            const int kjl = e0 / 24, d0 = e0 - kjl*24;
            *(float4*)&kv[kjl*28 + d0] = v;
        }
        __syncthreads();

        #pragma unroll
        for (int ul = 0; ul < 4; ul++) {
            const int kjl = lane + 32*ul;
            const int kj  = tt*128 + kjl;
            const ulonglong2* kp = (const ulonglong2*)&kv[kjl*28];
            ull acc2[4] = {};
            #pragma unroll
            for (int c = 0; c < 6; c++) {
                const ulonglong2 k2 = kp[c];
                FMA2(acc2[0], qr2[0][2*c], k2.x); FMA2(acc2[0], qr2[0][2*c+1], k2.y);
                FMA2(acc2[1], qr2[1][2*c], k2.x); FMA2(acc2[1], qr2[1][2*c+1], k2.y);
                FMA2(acc2[2], qr2[2][2*c], k2.x); FMA2(acc2[2], qr2[2][2*c+1], k2.y);
                FMA2(acc2[3], qr2[3][2*c], k2.x); FMA2(acc2[3], qr2[3][2*c+1], k2.y);
            }
            sc[(qib+0)*513 + kj] = LO_(acc2[0]) + HI_(acc2[0]) + bias_row[0*S_ + kj];
            sc[(qib+1)*513 + kj] = LO_(acc2[1]) + HI_(acc2[1]) + bias_row[1*S_ + kj];
            sc[(qib+2)*513 + kj] = LO_(acc2[2]) + HI_(acc2[2]) + bias_row[2*S_ + kj];
            sc[(qib+3)*513 + kj] = LO_(acc2[3]) + HI_(acc2[3]) + bias_row[3*S_ + kj];
        }
        __syncthreads();
    }

    #pragma unroll 1
    for (int rr = 0; rr < 4; rr++) {
        float* p = &sc[(qib + rr)*513];
        float mx = -1e30f;
        #pragma unroll
        for (int t = 0; t < 16; t++) mx = fmaxf(mx, p[lane + 32*t]);
        #pragma unroll
        for (int m = 16; m >= 1; m >>= 1) mx = fmaxf(mx, __shfl_xor_sync(0xffffffffu, mx, m));
        float e[16];
        float sum = 0.f;
        #pragma unroll
        for (int t = 0; t < 16; t++) { e[t] = __expf(p[lane + 32*t] - mx); sum += e[t]; }
        #pragma unroll
        for (int m = 16; m >= 1; m >>= 1) sum += __shfl_xor_sync(0xffffffffu, sum, m);
        const float rinv = 1.f / sum;
        #pragma unroll
        for (int t = 0; t < 16; t++) p[lane + 32*t] = e[t]*rinv;
    }
    __syncthreads();

    {
        const int qi = lane;
        ull acc2[12] = {};

        #pragma unroll 1
        for (int tt = 0; tt < 4; tt++) {
            const float4* src = (const float4*)&g_vt[(h*S_ + tt*128)*D_];
            #pragma unroll
            for (int it = 0; it < 3; it++) {
                const int f = tid + it*256;
                const float4 v = src[f];
                const int e0 = f*4;
                const int kjl = e0 / 24, d0 = e0 - kjl*24;
                *(float4*)&kv[kjl*28 + d0] = v;
            }
            __syncthreads();

            const float* prow = &sc[qi*513 + tt*128];
            #pragma unroll 2
            for (int kk = 0; kk < 16; kk++) {
                const int kjl = w*16 + kk;
                const float pv = prow[kjl];
                ull pvp; PACKDUP(pvp, pv);
                const ulonglong2* vp = (const ulonglong2*)&kv[kjl*28];
                #pragma unroll
                for (int c = 0; c < 6; c++) {
                    const ulonglong2 v2 = vp[c];
                    FMA2(acc2[2*c],   pvp, v2.x);
                    FMA2(acc2[2*c+1], pvp, v2.y);
                }
            }
            __syncthreads();
        }

        float* pp = &part[(w*32 + qi)*25];
        #pragma unroll
        for (int c = 0; c < 12; c++) {
            pp[2*c]   = LO_(acc2[c]);
            pp[2*c+1] = HI_(acc2[c]);
        }
    }
    __syncthreads();

    for (int e = tid; e < 32*24; e += 256) {
        const int qi = e / 24, d = e - qi*24;
        float sum = 0.f;
        #pragma unroll
        for (int ww = 0; ww < 8; ww++) sum += part[(ww*32 + qi)*25 + d];
        g_o[(qi0 + qi)*DS_ + h*D_ + d] = sum;
    }
}

// ============================================================
// out = (o*g) @ o_w^T : 32x64 tile, 512 thr, K split in halves
// (two 6-chunk pipelines -> half the per-block critical path).
// ============================================================
__global__ __launch_bounds__(512) void gemm_out_kernel(
    const float* __restrict__ W, float* __restrict__ C)
{
    __shared__ float As[2][32][36];
    __shared__ float Bs[2][32][68];
    __shared__ float Red[32][68];
    const int n0 = blockIdx.x*64, m0 = blockIdx.y*32;
    const int tid = threadIdx.x;
    const int kg  = tid >> 8;          // k-group 0/1
    const int t   = tid & 255;
    const int tx = t & 15, ty = t >> 4;
    const int lk = t & 31, lm = t >> 5;
    const int kbase = kg * 192;
    float acc[2][4] = {};
    float pa[4], pb[8];

    #pragma unroll
    for (int i = 0; i < 4; i++) {
        const int ai = (m0 + lm + 8*i)*DS_ + kbase + lk;
        pa[i] = g_o[ai] * g_g[ai];
    }
    #pragma unroll
    for (int i = 0; i < 8; i++) pb[i] = W[(n0 + lm + 8*i)*DS_ + kbase + lk];

    for (int k0 = 0; k0 < 192; k0 += 32) {
        #pragma unroll
        for (int i = 0; i < 4; i++) As[kg][lk][lm + 8*i] = pa[i];
        #pragma unroll
        for (int i = 0; i < 8; i++) Bs[kg][lk][lm + 8*i] = pb[i];
        __syncthreads();
        if (k0 + 32 < 192) {
            #pragma unroll
            for (int i = 0; i < 4; i++) {
                const int ai = (m0 + lm + 8*i)*DS_ + kbase + k0 + 32 + lk;
                pa[i] = g_o[ai] * g_g[ai];
            }
            #pragma unroll
            for (int i = 0; i < 8; i++)
                pb[i] = W[(n0 + lm + 8*i)*DS_ + kbase + k0 + 32 + lk];
        }
        #pragma unroll
        for (int kk = 0; kk < 32; kk++) {
            const float2 a  = *(const float2*)&As[kg][kk][ty*2];
            const float4 b = *(const float4*)&Bs[kg][kk][tx*4];
            acc[0][0] += a.x*b.x; acc[0][1] += a.x*b.y; acc[0][2] += a.x*b.z; acc[0][3] += a.x*b.w;
            acc[1][0] += a.y*b.x; acc[1][1] += a.y*b.y; acc[1][2] += a.y*b.z; acc[1][3] += a.y*b.w;
        }
        __syncthreads();
    }

    // combine k-halves through smem
    if (kg == 1) {
        #pragma unroll
        for (int i = 0; i < 2; i++)
            *(float4*)&Red[ty*2 + i][tx*4] =
                make_float4(acc[i][0], acc[i][1], acc[i][2], acc[i][3]);
    }
    __syncthreads();
    if (kg == 0) {
        #pragma unroll
        for (int i = 0; i < 2; i++) {
            const float4 r1 = *(const float4*)&Red[ty*2 + i][tx*4];
            *(float4*)&C[(m0 + ty*2 + i)*DS_ + n0 + tx*4] =
                make_float4(acc[i][0] + r1.x, acc[i][1] + r1.y,
                            acc[i][2] + r1.z, acc[i][3] + r1.w);
        }
    }
}

// ============================================================
extern "C" void kernel_launch(void* const* d_in, const int* in_sizes, int n_in,
                              void* d_out, int out_size)
{
    const float* s   = (const float*)d_in[0];
    const float* z   = (const float*)d_in[1];
    const float* msk = (const float*)d_in[2];
    const float* qw  = (const float*)d_in[3];
    const float* qb  = (const float*)d_in[4];
    const float* kw  = (const float*)d_in[5];
    const float* vw  = (const float*)d_in[6];
    const float* gw  = (const float*)d_in[7];
    const float* ow  = (const float*)d_in[8];
    const float* lnw = (const float*)d_in[9];
    const float* lnb = (const float*)d_in[10];
    const float* zw  = (const float*)d_in[11];
    float* out = (float*)d_out;

    const int smem_fused = (128*LDX_ + 16*CZ_ + 128) * 4;       // 76352 B
    const int smem_attn  = (32*513 + 128*28 + 8*32*25) * 4;     // 105600 B
    cudaFuncSetAttribute(fused_qkvg_bias_kernel,
                         cudaFuncAttributeMaxDynamicSharedMemorySize, smem_fused);
    cudaFuncSetAttribute(attn_kernel,
                         cudaFuncAttributeMaxDynamicSharedMemorySize, smem_attn);

    fused_qkvg_bias_kernel<<<NG_ + 2048, 256, smem_fused>>>(
        s, qw, qb, kw, vw, gw, z, msk, lnw, lnb, zw);
    attn_kernel<<<dim3(16, 16), 256, smem_attn>>>();
    gemm_out_kernel<<<dim3(6, 16), 512>>>(ow, out);
}

// round 16
// speedup vs baseline: 1.1525x; 1.0411x over previous
#include <cuda_runtime.h>

#define S_   512
#define H_   16
#define D_   24
#define DS_  384
#define CZ_  128
#define EPS_ 1e-5f
#define SCALE_ 0.20412414523193152f   // 24^-0.5

typedef unsigned long long ull;

// packed fp32x2 ops (bit-exact pairwise fp32; sm_100+ PTX)
#define FMA2(acc, a, b) \
    asm("fma.rn.f32x2 %0, %1, %2, %0;" : "+l"(acc) : "l"(a), "l"(b))
#define ADD2(acc, a) \
    asm("add.rn.f32x2 %0, %0, %1;" : "+l"(acc) : "l"(a))
#define PACKDUP(d, a) \
    asm("mov.b64 %0, {%1, %1};" : "=l"(d) : "r"(__float_as_uint(a)))
#define LO_(v) __uint_as_float((unsigned)(v))
#define HI_(v) __uint_as_float((unsigned)((v) >> 32))

// -------- scratch (no allocations allowed) --------
__device__ float g_qt[H_*S_*D_];      // [H][S][D], q pre-scaled by D^-0.5
__device__ float g_kt[H_*S_*D_];
__device__ float g_vt[H_*S_*D_];
__device__ float g_g[S_*DS_];
__device__ float g_o[S_*DS_];
__device__ float g_bias[H_*S_*S_];    // includes seq_mask

#define LDX_ 132
#define NG_  384     // gemm blocks in fused kernel

// ============================================================
// FUSED: blocks [0,NG_) = QKVG GEMMs, [NG_,NG_+2048) = bias.
// Bias path: LN folded into the matvec algebraically:
//   bias_h = rinv*(dot(x, lnw.*zw_h) - mu*C_h) + B_h + mask
// -> no LN smem pass, no shuffles, Y read only 2x.
// ============================================================
extern __shared__ float smx[];
__global__ __launch_bounds__(256) void fused_qkvg_bias_kernel(
    const float* __restrict__ s,
    const float* __restrict__ qw, const float* __restrict__ qb,
    const float* __restrict__ kw, const float* __restrict__ vw,
    const float* __restrict__ gw,
    const float* __restrict__ z, const float* __restrict__ mask,
    const float* __restrict__ lnw, const float* __restrict__ lnb,
    const float* __restrict__ zw)
{
    const int tid = threadIdx.x;

    if (blockIdx.x < NG_) {
        // ---------------- QKVG GEMM path (verified R12/R15 core) ----------------
        float* As = smx;             // [32][34]
        float* Bs = smx + 32*34;     // [32][68]
        const int b   = blockIdx.x;
        const int var = b / 96;
        const int r   = b % 96;
        const int n0  = (r % 6) * 64;
        const int m0  = (r / 6) * 32;
        const float* W = (var==0)?qw:(var==1)?kw:(var==2)?vw:gw;
        const int tx = tid & 15, ty = tid >> 4;
        const int lk = tid & 31, lm = tid >> 5;
        ull acc2[2][2] = {};
        float pa[4], pb[8];

        #pragma unroll
        for (int i = 0; i < 4; i++) pa[i] = s[(m0 + lm + 8*i)*DS_ + lk];
        #pragma unroll
        for (int i = 0; i < 8; i++) pb[i] = W[(n0 + lm + 8*i)*DS_ + lk];

        for (int k0 = 0; k0 < DS_; k0 += 32) {
            #pragma unroll
            for (int i = 0; i < 4; i++) As[lk*34 + lm + 8*i] = pa[i];
            #pragma unroll
            for (int i = 0; i < 8; i++) Bs[lk*68 + lm + 8*i] = pb[i];
            __syncthreads();
            if (k0 + 32 < DS_) {
                #pragma unroll
                for (int i = 0; i < 4; i++) pa[i] = s[(m0 + lm + 8*i)*DS_ + k0 + 32 + lk];
                #pragma unroll
                for (int i = 0; i < 8; i++) pb[i] = W[(n0 + lm + 8*i)*DS_ + k0 + 32 + lk];
            }
            #pragma unroll
            for (int kk = 0; kk < 32; kk++) {
                const float2 a = *(const float2*)&As[kk*34 + ty*2];
                const ulonglong2 b2 = *(const ulonglong2*)&Bs[kk*68 + tx*4];
                ull aa0, aa1;
                PACKDUP(aa0, a.x);
                PACKDUP(aa1, a.y);
                FMA2(acc2[0][0], aa0, b2.x); FMA2(acc2[0][1], aa0, b2.y);
                FMA2(acc2[1][0], aa1, b2.x); FMA2(acc2[1][1], aa1, b2.y);
            }
            __syncthreads();
        }

        const int col = n0 + tx*4;
        #pragma unroll
        for (int i = 0; i < 2; i++) {
            const int row = m0 + ty*2 + i;
            float4 rv = make_float4(LO_(acc2[i][0]), HI_(acc2[i][0]),
                                    LO_(acc2[i][1]), HI_(acc2[i][1]));
            if (var == 0) {
                rv.x += qb[col]; rv.y += qb[col+1]; rv.z += qb[col+2]; rv.w += qb[col+3];
                rv.x *= SCALE_; rv.y *= SCALE_; rv.z *= SCALE_; rv.w *= SCALE_;
            }
            if (var == 3) {
                rv.x = 1.f/(1.f+__expf(-rv.x));
                rv.y = 1.f/(1.f+__expf(-rv.y));
                rv.z = 1.f/(1.f+__expf(-rv.z));
                rv.w = 1.f/(1.f+__expf(-rv.w));
                *(float4*)&g_g[row*DS_ + col] = rv;
            } else {
                const int hh = col / D_;
                const int dd = col - hh*D_;
                float* dst = (var==0) ? g_qt : (var==1) ? g_kt : g_vt;
                *(float4*)&dst[(hh*S_ + row)*D_ + dd] = rv;
            }
        }
    } else {
        // ---------------- bias path: LN-folded matvec ----------------
        float* Y   = smx;                         // 128*132
        float* ZWp = smx + 128*LDX_;              // 16*128  (lnw .* zw)
        float* MS  = ZWp + 16*CZ_;                // 128
        float* PC  = MS + 128;                    // 512 partials for C_h
        float* PB  = PC + 512;                    // 512 partials for B_h
        float* CH  = PB + 512;                    // 16
        float* BH  = CH + 16;                     // 16
        const int r0  = (blockIdx.x - NG_) * 128;
        const int i_  = r0 >> 9;
        const int j0  = r0 & 511;

        // ---- stage z tile (coalesced) ----
        #pragma unroll
        for (int it = 0; it < 16; it++) {
            const int l = tid + it*256;
            const int row = l >> 5, c4 = l & 31;
            *(float4*)&Y[row*LDX_ + c4*4] =
                *(const float4*)&z[(size_t)(r0 + row)*CZ_ + c4*4];
        }
        // ---- stage ZWp = lnw.*zw + per-chunk partials for C_h, B_h ----
        #pragma unroll
        for (int it = 0; it < 2; it++) {
            const int idx = tid + it*256;          // 0..511
            const int c = (idx*4) & 127;
            const float4 zv = ((const float4*)zw)[idx];
            const float4 wv = *(const float4*)&lnw[c];
            const float4 bv = *(const float4*)&lnb[c];
            float4 pr;
            pr.x = zv.x*wv.x; pr.y = zv.y*wv.y; pr.z = zv.z*wv.z; pr.w = zv.w*wv.w;
            ((float4*)ZWp)[idx] = pr;
            PC[idx] = pr.x + pr.y + pr.z + pr.w;
            PB[idx] = zv.x*bv.x + zv.y*bv.y + zv.z*bv.z + zv.w*bv.w;
        }
        if (tid < 32) ((float4*)MS)[tid] = ((const float4*)(mask + j0))[tid];
        __syncthreads();

        if (tid < 16) {
            float c_ = 0.f, b_ = 0.f;
            #pragma unroll
            for (int ss = 0; ss < 32; ss++) {
                c_ += PC[tid*32 + ss];
                b_ += PB[tid*32 + ss];
            }
            CH[tid] = c_; BH[tid] = b_;
        }
        __syncthreads();

        // ---- fused stats + matvec: thread = (row = tid&127, 8 heads) ----
        {
            const int row = tid & 127;
            const int hb  = (tid >> 7) * 8;        // warp-uniform
            const ulonglong2* xp = (const ulonglong2*)&Y[row*LDX_];
            ull acc[8] = {};
            ull s2 = 0, q2 = 0;
            #pragma unroll 4
            for (int c4 = 0; c4 < 32; c4++) {
                const ulonglong2 x = xp[c4];
                ADD2(s2, x.x); ADD2(s2, x.y);
                FMA2(q2, x.x, x.x); FMA2(q2, x.y, x.y);
                #pragma unroll
                for (int h = 0; h < 8; h++) {
                    const ulonglong2 wv =
                        *(const ulonglong2*)&ZWp[(hb + h)*CZ_ + c4*4];
                    FMA2(acc[h], x.x, wv.x);
                    FMA2(acc[h], x.y, wv.y);
                }
            }
            const float sum = LO_(s2) + HI_(s2);
            const float ssq = LO_(q2) + HI_(q2);
            const float mu   = sum * (1.f/CZ_);
            const float var_ = ssq * (1.f/CZ_) - mu*mu;
            const float rinv = rsqrtf(var_ + EPS_);
            const float mk   = MS[row];
            #pragma unroll
            for (int h = 0; h < 8; h++) {
                const float d = LO_(acc[h]) + HI_(acc[h]);
                g_bias[((hb + h)*S_ + i_)*S_ + j0 + row] =
                    rinv*(d - mu*CH[hb + h]) + BH[hb + h] + mk;
            }
        }
    }
}

// ============================================================
// attention: unchanged R12 FFMA2 version (part of 145us baseline).
// ============================================================
extern __shared__ float sma[];
__global__ __launch_bounds__(256) void attn_kernel()
{
    float* sc   = sma;                       // [32][513]
    float* kv   = sma + 32*513;              // [128][28]
    float* part = sma + 32*513 + 128*28;     // [8][32][25]
    const int h    = blockIdx.y;
    const int qi0  = blockIdx.x * 32;
    const int tid  = threadIdx.x;
    const int lane = tid & 31;
    const int w    = tid >> 5;
    const int qib  = w * 4;

    ull qr2[4][12];
    #pragma unroll
    for (int i = 0; i < 4; i++) {
        const ulonglong2* qp = (const ulonglong2*)&g_qt[(h*S_ + qi0 + qib + i)*D_];
        #pragma unroll
        for (int c = 0; c < 6; c++) {
            const ulonglong2 v = qp[c];
            qr2[i][2*c] = v.x; qr2[i][2*c+1] = v.y;
        }
    }

    const float* bias_row = &g_bias[(h*S_ + qi0 + qib)*S_];

    #pragma unroll 1
    for (int tt = 0; tt < 4; tt++) {
        const float4* src = (const float4*)&g_kt[(h*S_ + tt*128)*D_];
        #pragma unroll
        for (int it = 0; it < 3; it++) {
            const int f = tid + it*256;
            const float4 v = src[f];
            const int e0 = f*4;
            const int kjl = e0 / 24, d0 = e0 - kjl*24;
            *(float4*)&kv[kjl*28 + d0] = v;
        }
        __syncthreads();

        #pragma unroll
        for (int ul = 0; ul < 4; ul++) {
            const int kjl = lane + 32*ul;
            const int kj  = tt*128 + kjl;
            const ulonglong2* kp = (const ulonglong2*)&kv[kjl*28];
            ull acc2[4] = {};
            #pragma unroll
            for (int c = 0; c < 6; c++) {
                const ulonglong2 k2 = kp[c];
                FMA2(acc2[0], qr2[0][2*c], k2.x); FMA2(acc2[0], qr2[0][2*c+1], k2.y);
                FMA2(acc2[1], qr2[1][2*c], k2.x); FMA2(acc2[1], qr2[1][2*c+1], k2.y);
                FMA2(acc2[2], qr2[2][2*c], k2.x); FMA2(acc2[2], qr2[2][2*c+1], k2.y);
                FMA2(acc2[3], qr2[3][2*c], k2.x); FMA2(acc2[3], qr2[3][2*c+1], k2.y);
            }
            sc[(qib+0)*513 + kj] = LO_(acc2[0]) + HI_(acc2[0]) + bias_row[0*S_ + kj];
            sc[(qib+1)*513 + kj] = LO_(acc2[1]) + HI_(acc2[1]) + bias_row[1*S_ + kj];
            sc[(qib+2)*513 + kj] = LO_(acc2[2]) + HI_(acc2[2]) + bias_row[2*S_ + kj];
            sc[(qib+3)*513 + kj] = LO_(acc2[3]) + HI_(acc2[3]) + bias_row[3*S_ + kj];
        }
        __syncthreads();
    }

    #pragma unroll 1
    for (int rr = 0; rr < 4; rr++) {
        float* p = &sc[(qib + rr)*513];
        float mx = -1e30f;
        #pragma unroll
        for (int t = 0; t < 16; t++) mx = fmaxf(mx, p[lane + 32*t]);
        #pragma unroll
        for (int m = 16; m >= 1; m >>= 1) mx = fmaxf(mx, __shfl_xor_sync(0xffffffffu, mx, m));
        float e[16];
        float sum = 0.f;
        #pragma unroll
        for (int t = 0; t < 16; t++) { e[t] = __expf(p[lane + 32*t] - mx); sum += e[t]; }
        #pragma unroll
        for (int m = 16; m >= 1; m >>= 1) sum += __shfl_xor_sync(0xffffffffu, sum, m);
        const float rinv = 1.f / sum;
        #pragma unroll
        for (int t = 0; t < 16; t++) p[lane + 32*t] = e[t]*rinv;
    }
    __syncthreads();

    {
        const int qi = lane;
        ull acc2[12] = {};

        #pragma unroll 1
        for (int tt = 0; tt < 4; tt++) {
            const float4* src = (const float4*)&g_vt[(h*S_ + tt*128)*D_];
            #pragma unroll
            for (int it = 0; it < 3; it++) {
                const int f = tid + it*256;
                const float4 v = src[f];
                const int e0 = f*4;
                const int kjl = e0 / 24, d0 = e0 - kjl*24;
                *(float4*)&kv[kjl*28 + d0] = v;
            }
            __syncthreads();

            const float* prow = &sc[qi*513 + tt*128];
            #pragma unroll 2
            for (int kk = 0; kk < 16; kk++) {
                const int kjl = w*16 + kk;
                const float pv = prow[kjl];
                ull pvp; PACKDUP(pvp, pv);
                const ulonglong2* vp = (const ulonglong2*)&kv[kjl*28];
                #pragma unroll
                for (int c = 0; c < 6; c++) {
                    const ulonglong2 v2 = vp[c];
                    FMA2(acc2[2*c],   pvp, v2.x);
                    FMA2(acc2[2*c+1], pvp, v2.y);
                }
            }
            __syncthreads();
        }

        float* pp = &part[(w*32 + qi)*25];
        #pragma unroll
        for (int c = 0; c < 12; c++) {
            pp[2*c]   = LO_(acc2[c]);
            pp[2*c+1] = HI_(acc2[c]);
        }
    }
    __syncthreads();

    for (int e = tid; e < 32*24; e += 256) {
        const int qi = e / 24, d = e - qi*24;
        float sum = 0.f;
        #pragma unroll
        for (int ww = 0; ww < 8; ww++) sum += part[(ww*32 + qi)*25 + d];
        g_o[(qi0 + qi)*DS_ + h*D_ + d] = sum;
    }
}

// ============================================================
// out = (o*g) @ o_w^T : 32x64 tile, 512 thr, K split in halves
// (unchanged from R15 baseline).
// ============================================================
__global__ __launch_bounds__(512) void gemm_out_kernel(
    const float* __restrict__ W, float* __restrict__ C)
{
    __shared__ float As[2][32][36];
    __shared__ float Bs[2][32][68];
    __shared__ float Red[32][68];
    const int n0 = blockIdx.x*64, m0 = blockIdx.y*32;
    const int tid = threadIdx.x;
    const int kg  = tid >> 8;
    const int t   = tid & 255;
    const int tx = t & 15, ty = t >> 4;
    const int lk = t & 31, lm = t >> 5;
    const int kbase = kg * 192;
    float acc[2][4] = {};
    float pa[4], pb[8];

    #pragma unroll
    for (int i = 0; i < 4; i++) {
        const int ai = (m0 + lm + 8*i)*DS_ + kbase + lk;
        pa[i] = g_o[ai] * g_g[ai];
    }
    #pragma unroll
    for (int i = 0; i < 8; i++) pb[i] = W[(n0 + lm + 8*i)*DS_ + kbase + lk];

    for (int k0 = 0; k0 < 192; k0 += 32) {
        #pragma unroll
        for (int i = 0; i < 4; i++) As[kg][lk][lm + 8*i] = pa[i];
        #pragma unroll
        for (int i = 0; i < 8; i++) Bs[kg][lk][lm + 8*i] = pb[i];
        __syncthreads();
        if (k0 + 32 < 192) {
            #pragma unroll
            for (int i = 0; i < 4; i++) {
                const int ai = (m0 + lm + 8*i)*DS_ + kbase + k0 + 32 + lk;
                pa[i] = g_o[ai] * g_g[ai];
            }
            #pragma unroll
            for (int i = 0; i < 8; i++)
                pb[i] = W[(n0 + lm + 8*i)*DS_ + kbase + k0 + 32 + lk];
        }
        #pragma unroll
        for (int kk = 0; kk < 32; kk++) {
            const float2 a  = *(const float2*)&As[kg][kk][ty*2];
            const float4 b = *(const float4*)&Bs[kg][kk][tx*4];
            acc[0][0] += a.x*b.x; acc[0][1] += a.x*b.y; acc[0][2] += a.x*b.z; acc[0][3] += a.x*b.w;
            acc[1][0] += a.y*b.x; acc[1][1] += a.y*b.y; acc[1][2] += a.y*b.z; acc[1][3] += a.y*b.w;
        }
        __syncthreads();
    }

    if (kg == 1) {
        #pragma unroll
        for (int i = 0; i < 2; i++)
            *(float4*)&Red[ty*2 + i][tx*4] =
                make_float4(acc[i][0], acc[i][1], acc[i][2], acc[i][3]);
    }
    __syncthreads();
    if (kg == 0) {
        #pragma unroll
        for (int i = 0; i < 2; i++) {
            const float4 r1 = *(const float4*)&Red[ty*2 + i][tx*4];
            *(float4*)&C[(m0 + ty*2 + i)*DS_ + n0 + tx*4] =
                make_float4(acc[i][0] + r1.x, acc[i][1] + r1.y,
                            acc[i][2] + r1.z, acc[i][3] + r1.w);
        }
    }
}

// ============================================================
extern "C" void kernel_launch(void* const* d_in, const int* in_sizes, int n_in,
                              void* d_out, int out_size)
{
    const float* s   = (const float*)d_in[0];
    const float* z   = (const float*)d_in[1];
    const float* msk = (const float*)d_in[2];
    const float* qw  = (const float*)d_in[3];
    const float* qb  = (const float*)d_in[4];
    const float* kw  = (const float*)d_in[5];
    const float* vw  = (const float*)d_in[6];
    const float* gw  = (const float*)d_in[7];
    const float* ow  = (const float*)d_in[8];
    const float* lnw = (const float*)d_in[9];
    const float* lnb = (const float*)d_in[10];
    const float* zw  = (const float*)d_in[11];
    float* out = (float*)d_out;

    // Y + ZWp + MS + PC + PB + CH + BH
    const int smem_fused = (128*LDX_ + 16*CZ_ + 128 + 512 + 512 + 16 + 16) * 4; // 80512 B
    const int smem_attn  = (32*513 + 128*28 + 8*32*25) * 4;                     // 105600 B
    cudaFuncSetAttribute(fused_qkvg_bias_kernel,
                         cudaFuncAttributeMaxDynamicSharedMemorySize, smem_fused);
    cudaFuncSetAttribute(attn_kernel,
                         cudaFuncAttributeMaxDynamicSharedMemorySize, smem_attn);

    fused_qkvg_bias_kernel<<<NG_ + 2048, 256, smem_fused>>>(
        s, qw, qb, kw, vw, gw, z, msk, lnw, lnb, zw);
    attn_kernel<<<dim3(16, 16), 256, smem_attn>>>();
    gemm_out_kernel<<<dim3(6, 16), 512>>>(ow, out);
}

// round 17
// speedup vs baseline: 1.2608x; 1.0940x over previous
#include <cuda_runtime.h>

#define S_   512
#define H_   16
#define D_   24
#define DS_  384
#define CZ_  128
#define EPS_ 1e-5f
#define SCALE_ 0.20412414523193152f   // 24^-0.5

typedef unsigned long long ull;

// packed fp32x2 ops (bit-exact pairwise fp32; sm_100+ PTX)
#define FMA2(acc, a, b) \
    asm("fma.rn.f32x2 %0, %1, %2, %0;" : "+l"(acc) : "l"(a), "l"(b))
#define ADD2(acc, a) \
    asm("add.rn.f32x2 %0, %0, %1;" : "+l"(acc) : "l"(a))
#define PACKDUP(d, a) \
    asm("mov.b64 %0, {%1, %1};" : "=l"(d) : "r"(__float_as_uint(a)))
#define LO_(v) __uint_as_float((unsigned)(v))
#define HI_(v) __uint_as_float((unsigned)((v) >> 32))

// -------- scratch (no allocations allowed) --------
__device__ float g_qt[H_*S_*D_];      // [H][S][D], q pre-scaled by D^-0.5
__device__ float g_kt[H_*S_*D_];
__device__ float g_vt[H_*S_*D_];
__device__ float g_g[S_*DS_];
__device__ float g_o[S_*DS_];
__device__ float g_bias[H_*S_*S_];    // includes seq_mask

#define LDX_ 132
#define NG_  384     // gemm blocks in fused kernel

// ============================================================
// FUSED: blocks [0,NG_) = QKVG GEMMs, [NG_,NG_+2048) = bias.
// Bias path smem trimmed to 75904B -> 3 blocks/SM:
//  - C_h/B_h reduced via warp shuffles (warp w owns heads w, w+8)
//  - mask read at store time (coalesced), no MS stage
// ============================================================
extern __shared__ float smx[];
__global__ __launch_bounds__(256) void fused_qkvg_bias_kernel(
    const float* __restrict__ s,
    const float* __restrict__ qw, const float* __restrict__ qb,
    const float* __restrict__ kw, const float* __restrict__ vw,
    const float* __restrict__ gw,
    const float* __restrict__ z, const float* __restrict__ mask,
    const float* __restrict__ lnw, const float* __restrict__ lnb,
    const float* __restrict__ zw)
{
    const int tid = threadIdx.x;

    if (blockIdx.x < NG_) {
        // ---------------- QKVG GEMM path (verified R12/R15 core) ----------------
        float* As = smx;             // [32][34]
        float* Bs = smx + 32*34;     // [32][68]
        const int b   = blockIdx.x;
        const int var = b / 96;
        const int r   = b % 96;
        const int n0  = (r % 6) * 64;
        const int m0  = (r / 6) * 32;
        const float* W = (var==0)?qw:(var==1)?kw:(var==2)?vw:gw;
        const int tx = tid & 15, ty = tid >> 4;
        const int lk = tid & 31, lm = tid >> 5;
        ull acc2[2][2] = {};
        float pa[4], pb[8];

        #pragma unroll
        for (int i = 0; i < 4; i++) pa[i] = s[(m0 + lm + 8*i)*DS_ + lk];
        #pragma unroll
        for (int i = 0; i < 8; i++) pb[i] = W[(n0 + lm + 8*i)*DS_ + lk];

        for (int k0 = 0; k0 < DS_; k0 += 32) {
            #pragma unroll
            for (int i = 0; i < 4; i++) As[lk*34 + lm + 8*i] = pa[i];
            #pragma unroll
            for (int i = 0; i < 8; i++) Bs[lk*68 + lm + 8*i] = pb[i];
            __syncthreads();
            if (k0 + 32 < DS_) {
                #pragma unroll
                for (int i = 0; i < 4; i++) pa[i] = s[(m0 + lm + 8*i)*DS_ + k0 + 32 + lk];
                #pragma unroll
                for (int i = 0; i < 8; i++) pb[i] = W[(n0 + lm + 8*i)*DS_ + k0 + 32 + lk];
            }
            #pragma unroll
            for (int kk = 0; kk < 32; kk++) {
                const float2 a = *(const float2*)&As[kk*34 + ty*2];
                const ulonglong2 b2 = *(const ulonglong2*)&Bs[kk*68 + tx*4];
                ull aa0, aa1;
                PACKDUP(aa0, a.x);
                PACKDUP(aa1, a.y);
                FMA2(acc2[0][0], aa0, b2.x); FMA2(acc2[0][1], aa0, b2.y);
                FMA2(acc2[1][0], aa1, b2.x); FMA2(acc2[1][1], aa1, b2.y);
            }
            __syncthreads();
        }

        const int col = n0 + tx*4;
        #pragma unroll
        for (int i = 0; i < 2; i++) {
            const int row = m0 + ty*2 + i;
            float4 rv = make_float4(LO_(acc2[i][0]), HI_(acc2[i][0]),
                                    LO_(acc2[i][1]), HI_(acc2[i][1]));
            if (var == 0) {
                rv.x += qb[col]; rv.y += qb[col+1]; rv.z += qb[col+2]; rv.w += qb[col+3];
                rv.x *= SCALE_; rv.y *= SCALE_; rv.z *= SCALE_; rv.w *= SCALE_;
            }
            if (var == 3) {
                rv.x = 1.f/(1.f+__expf(-rv.x));
                rv.y = 1.f/(1.f+__expf(-rv.y));
                rv.z = 1.f/(1.f+__expf(-rv.z));
                rv.w = 1.f/(1.f+__expf(-rv.w));
                *(float4*)&g_g[row*DS_ + col] = rv;
            } else {
                const int hh = col / D_;
                const int dd = col - hh*D_;
                float* dst = (var==0) ? g_qt : (var==1) ? g_kt : g_vt;
                *(float4*)&dst[(hh*S_ + row)*D_ + dd] = rv;
            }
        }
    } else {
        // ---------------- bias path: LN-folded matvec, slim smem ----------------
        float* Y   = smx;                         // 128*132
        float* ZWp = smx + 128*LDX_;              // 16*128  (lnw .* zw)
        float* CH  = ZWp + 16*CZ_;                // 16
        float* BH  = CH + 16;                     // 16
        const int lane = tid & 31;
        const int r0  = (blockIdx.x - NG_) * 128;
        const int i_  = r0 >> 9;
        const int j0  = r0 & 511;

        // ---- stage z tile (coalesced) ----
        #pragma unroll
        for (int it = 0; it < 16; it++) {
            const int l = tid + it*256;
            const int row = l >> 5, c4 = l & 31;
            *(float4*)&Y[row*LDX_ + c4*4] =
                *(const float4*)&z[(size_t)(r0 + row)*CZ_ + c4*4];
        }
        // ---- stage ZWp = lnw.*zw; C_h/B_h via warp reduction ----
        // it=0: idx=tid (heads 0..7, warp w -> head w)
        // it=1: idx=tid+256 (heads 8..15, warp w -> head w+8)
        #pragma unroll
        for (int it = 0; it < 2; it++) {
            const int idx = tid + it*256;          // 0..511
            const int c = (idx*4) & 127;
            const float4 zv = ((const float4*)zw)[idx];
            const float4 wv = *(const float4*)&lnw[c];
            const float4 bv = *(const float4*)&lnb[c];
            float4 pr;
            pr.x = zv.x*wv.x; pr.y = zv.y*wv.y; pr.z = zv.z*wv.z; pr.w = zv.w*wv.w;
            ((float4*)ZWp)[idx] = pr;
            float pc = pr.x + pr.y + pr.z + pr.w;
            float pbv = zv.x*bv.x + zv.y*bv.y + zv.z*bv.z + zv.w*bv.w;
            #pragma unroll
            for (int m = 16; m >= 1; m >>= 1) {
                pc  += __shfl_xor_sync(0xffffffffu, pc,  m);
                pbv += __shfl_xor_sync(0xffffffffu, pbv, m);
            }
            if (lane == 0) {
                const int hh = idx >> 5;
                CH[hh] = pc; BH[hh] = pbv;
            }
        }
        __syncthreads();

        // ---- fused stats + matvec: thread = (row = tid&127, 8 heads) ----
        {
            const int row = tid & 127;
            const int hb  = (tid >> 7) * 8;        // warp-uniform
            const ulonglong2* xp = (const ulonglong2*)&Y[row*LDX_];
            ull acc[8] = {};
            ull s2 = 0, q2 = 0;
            #pragma unroll 4
            for (int c4 = 0; c4 < 32; c4++) {
                const ulonglong2 x = xp[c4];
                ADD2(s2, x.x); ADD2(s2, x.y);
                FMA2(q2, x.x, x.x); FMA2(q2, x.y, x.y);
                #pragma unroll
                for (int h = 0; h < 8; h++) {
                    const ulonglong2 wv =
                        *(const ulonglong2*)&ZWp[(hb + h)*CZ_ + c4*4];
                    FMA2(acc[h], x.x, wv.x);
                    FMA2(acc[h], x.y, wv.y);
                }
            }
            const float sum = LO_(s2) + HI_(s2);
            const float ssq = LO_(q2) + HI_(q2);
            const float mu   = sum * (1.f/CZ_);
            const float var_ = ssq * (1.f/CZ_) - mu*mu;
            const float rinv = rsqrtf(var_ + EPS_);
            const float mk   = __ldg(&mask[j0 + row]);   // coalesced over rows
            #pragma unroll
            for (int h = 0; h < 8; h++) {
                const float d = LO_(acc[h]) + HI_(acc[h]);
                g_bias[((hb + h)*S_ + i_)*S_ + j0 + row] =
                    rinv*(d - mu*CH[hb + h]) + BH[hb + h] + mk;
            }
        }
    }
}

// ============================================================
// attention: unchanged R12 FFMA2 version (part of 139us baseline).
// ============================================================
extern __shared__ float sma[];
__global__ __launch_bounds__(256) void attn_kernel()
{
    float* sc   = sma;                       // [32][513]
    float* kv   = sma + 32*513;              // [128][28]
    float* part = sma + 32*513 + 128*28;     // [8][32][25]
    const int h    = blockIdx.y;
    const int qi0  = blockIdx.x * 32;
    const int tid  = threadIdx.x;
    const int lane = tid & 31;
    const int w    = tid >> 5;
    const int qib  = w * 4;

    ull qr2[4][12];
    #pragma unroll
    for (int i = 0; i < 4; i++) {
        const ulonglong2* qp = (const ulonglong2*)&g_qt[(h*S_ + qi0 + qib + i)*D_];
        #pragma unroll
        for (int c = 0; c < 6; c++) {
            const ulonglong2 v = qp[c];
            qr2[i][2*c] = v.x; qr2[i][2*c+1] = v.y;
        }
    }

    const float* bias_row = &g_bias[(h*S_ + qi0 + qib)*S_];

    #pragma unroll 1
    for (int tt = 0; tt < 4; tt++) {
        const float4* src = (const float4*)&g_kt[(h*S_ + tt*128)*D_];
        #pragma unroll
        for (int it = 0; it < 3; it++) {
            const int f = tid + it*256;
            const float4 v = src[f];
            const int e0 = f*4;
            const int kjl = e0 / 24, d0 = e0 - kjl*24;
            *(float4*)&kv[kjl*28 + d0] = v;
        }
        __syncthreads();

        #pragma unroll
        for (int ul = 0; ul < 4; ul++) {
            const int kjl = lane + 32*ul;
            const int kj  = tt*128 + kjl;
            const ulonglong2* kp = (const ulonglong2*)&kv[kjl*28];
            ull acc2[4] = {};
            #pragma unroll
            for (int c = 0; c < 6; c++) {
                const ulonglong2 k2 = kp[c];
                FMA2(acc2[0], qr2[0][2*c], k2.x); FMA2(acc2[0], qr2[0][2*c+1], k2.y);
                FMA2(acc2[1], qr2[1][2*c], k2.x); FMA2(acc2[1], qr2[1][2*c+1], k2.y);
                FMA2(acc2[2], qr2[2][2*c], k2.x); FMA2(acc2[2], qr2[2][2*c+1], k2.y);
                FMA2(acc2[3], qr2[3][2*c], k2.x); FMA2(acc2[3], qr2[3][2*c+1], k2.y);
            }
            sc[(qib+0)*513 + kj] = LO_(acc2[0]) + HI_(acc2[0]) + bias_row[0*S_ + kj];
            sc[(qib+1)*513 + kj] = LO_(acc2[1]) + HI_(acc2[1]) + bias_row[1*S_ + kj];
            sc[(qib+2)*513 + kj] = LO_(acc2[2]) + HI_(acc2[2]) + bias_row[2*S_ + kj];
            sc[(qib+3)*513 + kj] = LO_(acc2[3]) + HI_(acc2[3]) + bias_row[3*S_ + kj];
        }
        __syncthreads();
    }

    #pragma unroll 1
    for (int rr = 0; rr < 4; rr++) {
        float* p = &sc[(qib + rr)*513];
        float mx = -1e30f;
        #pragma unroll
        for (int t = 0; t < 16; t++) mx = fmaxf(mx, p[lane + 32*t]);
        #pragma unroll
        for (int m = 16; m >= 1; m >>= 1) mx = fmaxf(mx, __shfl_xor_sync(0xffffffffu, mx, m));
        float e[16];
        float sum = 0.f;
        #pragma unroll
        for (int t = 0; t < 16; t++) { e[t] = __expf(p[lane + 32*t] - mx); sum += e[t]; }
        #pragma unroll
        for (int m = 16; m >= 1; m >>= 1) sum += __shfl_xor_sync(0xffffffffu, sum, m);
        const float rinv = 1.f / sum;
        #pragma unroll
        for (int t = 0; t < 16; t++) p[lane + 32*t] = e[t]*rinv;
    }
    __syncthreads();

    {
        const int qi = lane;
        ull acc2[12] = {};

        #pragma unroll 1
        for (int tt = 0; tt < 4; tt++) {
            const float4* src = (const float4*)&g_vt[(h*S_ + tt*128)*D_];
            #pragma unroll
            for (int it = 0; it < 3; it++) {
                const int f = tid + it*256;
                const float4 v = src[f];
                const int e0 = f*4;
                const int kjl = e0 / 24, d0 = e0 - kjl*24;
                *(float4*)&kv[kjl*28 + d0] = v;
            }
            __syncthreads();

            const float* prow = &sc[qi*513 + tt*128];
            #pragma unroll 2
            for (int kk = 0; kk < 16; kk++) {
                const int kjl = w*16 + kk;
                const float pv = prow[kjl];
                ull pvp; PACKDUP(pvp, pv);
                const ulonglong2* vp = (const ulonglong2*)&kv[kjl*28];
                #pragma unroll
                for (int c = 0; c < 6; c++) {
                    const ulonglong2 v2 = vp[c];
                    FMA2(acc2[2*c],   pvp, v2.x);
                    FMA2(acc2[2*c+1], pvp, v2.y);
                }
            }
            __syncthreads();
        }

        float* pp = &part[(w*32 + qi)*25];
        #pragma unroll
        for (int c = 0; c < 12; c++) {
            pp[2*c]   = LO_(acc2[c]);
            pp[2*c+1] = HI_(acc2[c]);
        }
    }
    __syncthreads();

    for (int e = tid; e < 32*24; e += 256) {
        const int qi = e / 24, d = e - qi*24;
        float sum = 0.f;
        #pragma unroll
        for (int ww = 0; ww < 8; ww++) sum += part[(ww*32 + qi)*25 + d];
        g_o[(qi0 + qi)*DS_ + h*D_ + d] = sum;
    }
}

// ============================================================
// out = (o*g) @ o_w^T : 32x64 tile, 512 thr, K split in halves
// (unchanged from R15/R16 baseline).
// ============================================================
__global__ __launch_bounds__(512) void gemm_out_kernel(
    const float* __restrict__ W, float* __restrict__ C)
{
    __shared__ float As[2][32][36];
    __shared__ float Bs[2][32][68];
    __shared__ float Red[32][68];
    const int n0 = blockIdx.x*64, m0 = blockIdx.y*32;
    const int tid = threadIdx.x;
    const int kg  = tid >> 8;
    const int t   = tid & 255;
    const int tx = t & 15, ty = t >> 4;
    const int lk = t & 31, lm = t >> 5;
    const int kbase = kg * 192;
    float acc[2][4] = {};
    float pa[4], pb[8];

    #pragma unroll
    for (int i = 0; i < 4; i++) {
        const int ai = (m0 + lm + 8*i)*DS_ + kbase + lk;
        pa[i] = g_o[ai] * g_g[ai];
    }
    #pragma unroll
    for (int i = 0; i < 8; i++) pb[i] = W[(n0 + lm + 8*i)*DS_ + kbase + lk];

    for (int k0 = 0; k0 < 192; k0 += 32) {
        #pragma unroll
        for (int i = 0; i < 4; i++) As[kg][lk][lm + 8*i] = pa[i];
        #pragma unroll
        for (int i = 0; i < 8; i++) Bs[kg][lk][lm + 8*i] = pb[i];
        __syncthreads();
        if (k0 + 32 < 192) {
            #pragma unroll
            for (int i = 0; i < 4; i++) {
                const int ai = (m0 + lm + 8*i)*DS_ + kbase + k0 + 32 + lk;
                pa[i] = g_o[ai] * g_g[ai];
            }
            #pragma unroll
            for (int i = 0; i < 8; i++)
                pb[i] = W[(n0 + lm + 8*i)*DS_ + kbase + k0 + 32 + lk];
        }
        #pragma unroll
        for (int kk = 0; kk < 32; kk++) {
            const float2 a  = *(const float2*)&As[kg][kk][ty*2];
            const float4 b = *(const float4*)&Bs[kg][kk][tx*4];
            acc[0][0] += a.x*b.x; acc[0][1] += a.x*b.y; acc[0][2] += a.x*b.z; acc[0][3] += a.x*b.w;
            acc[1][0] += a.y*b.x; acc[1][1] += a.y*b.y; acc[1][2] += a.y*b.z; acc[1][3] += a.y*b.w;
        }
        __syncthreads();
    }

    if (kg == 1) {
        #pragma unroll
        for (int i = 0; i < 2; i++)
            *(float4*)&Red[ty*2 + i][tx*4] =
                make_float4(acc[i][0], acc[i][1], acc[i][2], acc[i][3]);
    }
    __syncthreads();
    if (kg == 0) {
        #pragma unroll
        for (int i = 0; i < 2; i++) {
            const float4 r1 = *(const float4*)&Red[ty*2 + i][tx*4];
            *(float4*)&C[(m0 + ty*2 + i)*DS_ + n0 + tx*4] =
                make_float4(acc[i][0] + r1.x, acc[i][1] + r1.y,
                            acc[i][2] + r1.z, acc[i][3] + r1.w);
        }
    }
}

// ============================================================
extern "C" void kernel_launch(void* const* d_in, const int* in_sizes, int n_in,
                              void* d_out, int out_size)
{
    const float* s   = (const float*)d_in[0];
    const float* z   = (const float*)d_in[1];
    const float* msk = (const float*)d_in[2];
    const float* qw  = (const float*)d_in[3];
    const float* qb  = (const float*)d_in[4];
    const float* kw  = (const float*)d_in[5];
    const float* vw  = (const float*)d_in[6];
    const float* gw  = (const float*)d_in[7];
    const float* ow  = (const float*)d_in[8];
    const float* lnw = (const float*)d_in[9];
    const float* lnb = (const float*)d_in[10];
    const float* zw  = (const float*)d_in[11];
    float* out = (float*)d_out;

    // Y + ZWp + CH + BH = (16896 + 2048 + 16 + 16)*4 = 75904 B -> 3 blocks/SM
    const int smem_fused = (128*LDX_ + 16*CZ_ + 16 + 16) * 4;
    const int smem_attn  = (32*513 + 128*28 + 8*32*25) * 4;     // 105600 B
    cudaFuncSetAttribute(fused_qkvg_bias_kernel,
                         cudaFuncAttributeMaxDynamicSharedMemorySize, smem_fused);
    cudaFuncSetAttribute(attn_kernel,
                         cudaFuncAttributeMaxDynamicSharedMemorySize, smem_attn);

    fused_qkvg_bias_kernel<<<NG_ + 2048, 256, smem_fused>>>(
        s, qw, qb, kw, vw, gw, z, msk, lnw, lnb, zw);
    attn_kernel<<<dim3(16, 16), 256, smem_attn>>>();
    gemm_out_kernel<<<dim3(6, 16), 512>>>(ow, out);
}